// round 17
// baseline (speedup 1.0000x reference)
#include <cuda_runtime.h>
#include <math.h>

// DifferentiableICP: B=32, N=M=2048, 5 soft-ICP iterations.
// R17: R16 body + Programmatic Dependent Launch (PDL). Each iter kernel
//      triggers launch completion at its head; the NEXT kernel's CTAs start
//      early (160 spare slots + freed slots during the tail), stage their
//      24KB smem from RAW target (PDL-safe: reads only kernel inputs), then
//      cudaGridDependencySynchronize() before reading g_part/g_Tbuf.
//      Hides staging + head + launch gap in the primary's retirement tail.
//      R16's lesson: staging-compute costs ~1.5us/iter when serial -> make it
//      concurrent instead of deleting it. No init kernel; 6 launches total.
// Mainloop unchanged from R9 (best measured): f32x2 FMA dot-form logit,
// ex2.approx.ftz.f32, 2 LDS/pair, MUFU-paced ~30us/iter floor.

#define BB 32
#define NN 2048
#define MM 2048
#define ITERS 5
#define CHUNKS 32                    // CTAs per batch
#define ROWS_PER_CTA (NN / CHUNKS)   // 64
#define RPT 2                        // rows per thread
#define MSPLIT 4                     // warps per CTA == M segments
#define TPB (32 * MSPLIT)            // 128
#define NPAIR (MM / 2)               // 1024 packed target pairs
#define SEGPAIRS (NPAIR / MSPLIT)    // 256 pairs per segment

typedef unsigned long long ull;

// Scratch (allocation-free rule: __device__ globals)
__device__ float g_Tbuf[2][BB][4];   // (cos,sin,tx,ty), double-buffered
__device__ float g_part[BB][CHUNKS][8];

// ---- packed f32x2 helpers (PTX-only; ptxas never auto-fuses FFMA2) --------
__device__ __forceinline__ ull fma2(ull a, ull b, ull c) {
    ull d; asm("fma.rn.f32x2 %0, %1, %2, %3;" : "=l"(d) : "l"(a), "l"(b), "l"(c));
    return d;
}
__device__ __forceinline__ ull add2(ull a, ull b) {
    ull d; asm("add.rn.f32x2 %0, %1, %2;" : "=l"(d) : "l"(a), "l"(b));
    return d;
}
__device__ __forceinline__ ull pack2(float lo, float hi) {
    ull d; asm("mov.b64 %0, {%1, %2};" : "=l"(d) : "f"(lo), "f"(hi));
    return d;
}
__device__ __forceinline__ void unpack2(ull v, float& lo, float& hi) {
    asm("mov.b64 {%0, %1}, %2;" : "=f"(lo), "=f"(hi) : "l"(v));
}
__device__ __forceinline__ float ex2f(float x) {
    float e; asm("ex2.approx.ftz.f32 %0, %1;" : "=f"(e) : "f"(x));
    return e;
}

// ---------------------------------------------------------------------------
// Shared update math: given the 8 reduced sums p[] and T_old, produce T_new.
// R_delta = V @ U^T (SVD of H) == orthogonal polar factor of H^T, closed form.
// MUST be called with identical inputs everywhere it's used (bit-identical).
// ---------------------------------------------------------------------------
__device__ __forceinline__ void icp_compose(const float p[8],
                                            float cc, float ss, float ttx, float tty,
                                            float& c2, float& s2, float& tx2, float& ty2) {
    const float invN = 1.0f / (float)NN;
    const float csx = p[0] * invN, csy = p[1] * invN;
    const float ctx = p[2] * invN, cty = p[3] * invN;

    const float h00 = p[4] - p[0] * p[2] * invN;
    const float h01 = p[5] - p[0] * p[3] * invN;
    const float h10 = p[6] - p[1] * p[2] * invN;
    const float h11 = p[7] - p[1] * p[3] * invN;

    const float E  = 0.5f * (h00 + h11);
    const float F  = 0.5f * (h00 - h11);
    const float G  = 0.5f * (h01 + h10);
    const float Hh = 0.5f * (h01 - h10);
    const float det = h00 * h11 - h01 * h10;

    float r00, r01, r10, r11;
    if (det >= 0.0f) {           // rotation branch
        float iq = rsqrtf(E * E + Hh * Hh);
        r00 =  E * iq;  r01 = -Hh * iq;
        r10 = Hh * iq;  r11 =  E * iq;
    } else {                      // reflection branch
        float ir = rsqrtf(F * F + G * G);
        r00 =  F * ir;  r01 =  G * ir;
        r10 =  G * ir;  r11 = -F * ir;
    }

    const float ih = rsqrtf(r00 * r00 + r10 * r10);
    const float cD = r00 * ih;
    const float sD = r10 * ih;
    const float tDx = ctx - (r00 * csx + r01 * csy);
    const float tDy = cty - (r10 * csx + r11 * csy);

    c2  = cD * cc - sD * ss;
    s2  = sD * cc + cD * ss;
    tx2 = cD * ttx - sD * tty + tDx;
    ty2 = sD * ttx + cD * tty + tDy;
}

// ---------------------------------------------------------------------------
// Iter kernel `it` (0..4). grid = BB*CHUNKS = 1024 CTAs, block = 128.
// PDL order: trigger -> stage smem from raw target -> grid-dep sync ->
//            head (reduce prev g_part, compose T) -> mainloop -> write g_part.
// ---------------------------------------------------------------------------
__global__ void __launch_bounds__(TPB, 8)
icp_iter_kernel(const float* __restrict__ source,
                const float* __restrict__ target,
                const float* __restrict__ init_t, int it) {
    __shared__ ulonglong2 sUV[NPAIR];                     // 16 KB
    __shared__ ull        sW[NPAIR];                      // 8 KB
    __shared__ float4     sRow[MSPLIT - 1][ROWS_PER_CTA]; // 3 KB

    const int b     = blockIdx.x >> 5;
    const int chunk = blockIdx.x & 31;
    const int tid   = threadIdx.x;
    const int lane  = tid & 31;
    const int warp  = tid >> 5;          // == M-segment

#if __CUDA_ARCH__ >= 900
    // Let the NEXT kernel start launching immediately (its pre-sync phase
    // only touches kernel inputs + its own smem; correctness is protected by
    // its cudaGridDependencySynchronize before reading g_part/g_Tbuf).
    cudaTriggerProgrammaticLaunchCompletion();
#endif

    const float L2E = 1.4426950408889634f;

    // Stage constants computed from raw target (coalesced 16B loads).
    // PDL-safe: reads only the kernel's const inputs.
    for (int i = tid; i < NPAIR; i += TPB) {
        const float4 f = reinterpret_cast<const float4*>(target)[(size_t)b * NPAIR + i];
        ulonglong2 uv;
        uv.x = pack2(2.0f * L2E * f.x, 2.0f * L2E * f.z);
        uv.y = pack2(2.0f * L2E * f.y, 2.0f * L2E * f.w);
        sUV[i] = uv;
        sW[i]  = pack2(-L2E * (f.x * f.x + f.y * f.y),
                       -L2E * (f.z * f.z + f.w * f.w));
    }

#if __CUDA_ARCH__ >= 900
    // Wait for the previous kernel's g_part/g_Tbuf writes to be visible.
    if (it > 0) cudaGridDependencySynchronize();
#endif

    // ---- compute this iteration's transform (redundant per CTA/warp) ----
    const int rd = it & 1;
    float c, s, tx, ty;
    {
        if (it == 0) {
            const float th = init_t[b * 3 + 0];
            c  = cosf(th);
            s  = sinf(th);
            tx = init_t[b * 3 + 1];
            ty = init_t[b * 3 + 2];
        } else {
            const float cc  = g_Tbuf[rd][b][0];
            const float ss  = g_Tbuf[rd][b][1];
            const float ttx = g_Tbuf[rd][b][2];
            const float tty = g_Tbuf[rd][b][3];
            // lane == chunk index: reduce previous iteration's partials
            float p[8];
            #pragma unroll
            for (int k = 0; k < 8; ++k) p[k] = g_part[b][lane][k];
            #pragma unroll
            for (int off = 16; off; off >>= 1)
                #pragma unroll
                for (int k = 0; k < 8; ++k)
                    p[k] += __shfl_xor_sync(0xFFFFFFFFu, p[k], off);
            icp_compose(p, cc, ss, ttx, tty, c, s, tx, ty);
        }
        // persist T_it for the next kernel (double-buffered: no read/write race)
        if (chunk == 0 && tid == 0) {
            g_Tbuf[rd ^ 1][b][0] = c;
            g_Tbuf[rd ^ 1][b][1] = s;
            g_Tbuf[rd ^ 1][b][2] = tx;
            g_Tbuf[rd ^ 1][b][3] = ty;
        }
    }

    // st = R*source + t for this thread's 2 rows
    float sx[RPT], sy[RPT];
    ull sx2[RPT], sy2[RPT];
    #pragma unroll
    for (int k = 0; k < RPT; ++k) {
        const int row = chunk * ROWS_PER_CTA + lane + 32 * k;
        const float2 sv = reinterpret_cast<const float2*>(source)[(size_t)b * NN + row];
        sx[k] = c * sv.x - s * sv.y + tx;
        sy[k] = s * sv.x + c * sv.y + ty;
        sx2[k] = pack2(sx[k], sx[k]);
        sy2[k] = pack2(sy[k], sy[k]);
    }

    __syncthreads();

    // Packed single-pass softmax-weighted sums: 2 LDS/pair, reused x2 rows.
    ull se2[RPT], au2[RPT], av2[RPT];
    #pragma unroll
    for (int k = 0; k < RPT; ++k) { se2[k] = 0ull; au2[k] = 0ull; av2[k] = 0ull; }

    const int p0 = warp * SEGPAIRS;
    #pragma unroll 4
    for (int p = p0; p < p0 + SEGPAIRS; ++p) {
        const ulonglong2 uv = sUV[p];
        const ull u2 = uv.x;
        const ull v2 = uv.y;
        const ull w2 = sW[p];
        #pragma unroll
        for (int k = 0; k < RPT; ++k) {
            ull y2 = fma2(sx2[k], u2, w2);
            y2 = fma2(sy2[k], v2, y2);
            float y0, y1; unpack2(y2, y0, y1);
            const ull e2 = pack2(ex2f(y0), ex2f(y1));
            se2[k] = add2(se2[k], e2);
            au2[k] = fma2(e2, u2, au2[k]);
            av2[k] = fma2(e2, v2, av2[k]);
        }
    }

    // Horizontal add of the packed halves (fixed order: lo + hi)
    float se[RPT], au[RPT], av[RPT];
    #pragma unroll
    for (int k = 0; k < RPT; ++k) {
        float a0, a1;
        unpack2(se2[k], a0, a1); se[k] = a0 + a1;
        unpack2(au2[k], a0, a1); au[k] = a0 + a1;
        unpack2(av2[k], a0, a1); av[k] = a0 + a1;
    }

    // Publish segment partials (warps 1..3), combine in warp 0 (fixed order)
    if (warp > 0) {
        #pragma unroll
        for (int k = 0; k < RPT; ++k)
            sRow[warp - 1][lane + 32 * k] = make_float4(se[k], au[k], av[k], 0.0f);
    }
    __syncthreads();

    if (warp == 0) {
        float p[8];
        #pragma unroll
        for (int i = 0; i < 8; ++i) p[i] = 0.0f;

        #pragma unroll
        for (int k = 0; k < RPT; ++k) {
            float sek = se[k], auk = au[k], avk = av[k];
            #pragma unroll
            for (int q = 0; q < MSPLIT - 1; ++q) {   // fixed order seg1..3
                const float4 f = sRow[q][lane + 32 * k];
                sek += f.x; auk += f.y; avk += f.z;
            }
            const float KINV = 0.34657359027997264f; // ln(2)/2 (undo folded 2*log2e)
            const float inv = KINV / sek;
            const float tcx = auk * inv;
            const float tcy = avk * inv;
            // fixed-order accumulation over k
            p[0] += sx[k];        p[1] += sy[k];
            p[2] += tcx;          p[3] += tcy;
            p[4] += sx[k] * tcx;  p[5] += sx[k] * tcy;
            p[6] += sy[k] * tcx;  p[7] += sy[k] * tcy;
        }

        // Deterministic warp butterfly
        #pragma unroll
        for (int off = 16; off; off >>= 1)
            #pragma unroll
            for (int i = 0; i < 8; ++i)
                p[i] += __shfl_xor_sync(0xFFFFFFFFu, p[i], off);

        if (lane == 0) {
            #pragma unroll
            for (int i = 0; i < 8; ++i) g_part[b][chunk][i] = p[i];
        }
    }
}

// ---------------------------------------------------------------------------
// Final kernel: reduce last iteration's partials, compose T_5, write output.
// grid = BB x 32 threads. PDL: sync before reading g_part/g_Tbuf.
// ---------------------------------------------------------------------------
__global__ void icp_final_kernel(float* __restrict__ out) {
    const int b = blockIdx.x;
    const int t = threadIdx.x;

#if __CUDA_ARCH__ >= 900
    cudaGridDependencySynchronize();
#endif

    float p[8];
    #pragma unroll
    for (int k = 0; k < 8; ++k) p[k] = g_part[b][t][k];
    #pragma unroll
    for (int off = 16; off; off >>= 1)
        #pragma unroll
        for (int k = 0; k < 8; ++k)
            p[k] += __shfl_xor_sync(0xFFFFFFFFu, p[k], off);

    if (t == 0) {
        const int rd = ITERS & 1;   // buffer holding T_{ITERS-1}
        float c2, s2, tx2, ty2;
        icp_compose(p, g_Tbuf[rd][b][0], g_Tbuf[rd][b][1],
                       g_Tbuf[rd][b][2], g_Tbuf[rd][b][3],
                    c2, s2, tx2, ty2);
        out[b * 3 + 0] = atan2f(s2, c2);
        out[b * 3 + 1] = tx2;
        out[b * 3 + 2] = ty2;
    }
}

// ---------------------------------------------------------------------------
extern "C" void kernel_launch(void* const* d_in, const int* in_sizes, int n_in,
                              void* d_out, int out_size) {
    const float* source = (const float*)d_in[0];   // (32, 2048, 2)
    const float* target = (const float*)d_in[1];   // (32, 2048, 2)
    const float* init_t = (const float*)d_in[2];   // (32, 3)
    float* out = (float*)d_out;                    // (32, 3)

    cudaLaunchAttribute attrs[1];
    attrs[0].id = cudaLaunchAttributeProgrammaticStreamSerialization;
    attrs[0].val.programmaticStreamSerializationAllowed = 1;

    cudaLaunchConfig_t cfg = {};
    cfg.gridDim = dim3(BB * CHUNKS);
    cfg.blockDim = dim3(TPB);
    cfg.dynamicSmemBytes = 0;
    cfg.stream = 0;

    for (int it = 0; it < ITERS; ++it) {
        if (it == 0) {
            // first kernel: no PDL predecessor
            cfg.attrs = nullptr;
            cfg.numAttrs = 0;
        } else {
            cfg.attrs = attrs;
            cfg.numAttrs = 1;
        }
        cudaLaunchKernelEx(&cfg, icp_iter_kernel, source, target, init_t, it);
    }

    cudaLaunchConfig_t cfgF = {};
    cfgF.gridDim = dim3(BB);
    cfgF.blockDim = dim3(32);
    cfgF.dynamicSmemBytes = 0;
    cfgF.stream = 0;
    cfgF.attrs = attrs;
    cfgF.numAttrs = 1;
    cudaLaunchKernelEx(&cfgF, icp_final_kernel, out);
}